// round 11
// baseline (speedup 1.0000x reference)
#include <cuda_runtime.h>
#include <cuda_fp16.h>
#include <cstdint>

// ---------------------------------------------------------------------------
// Problem dims (fixed by the dataset)
// ---------------------------------------------------------------------------
#define NTOK 8192          // B*S tokens
#define DIM  1024          // model dim
#define HID  4096          // hidden dim
#define NE   8             // experts
#define CAP  8192          // per-expert token capacity (max possible)

#define BM 128
#define BN 128
#define BK 64
#define LDA (BK + 8)       // 72 halves (144B rows; conflict-free for ldmatrix)
#define LDB (BN + 8)       // 136 halves (272B rows; conflict-free for ldmatrix)
#define ASTAGE (BM * LDA * 2)      // 18432 B per A stage
#define BSTAGE (BK * LDB * 2)      // 17408 B per B stage
// 2 stages: (18432+17408)*2 = 71680 B per CTA -> 2 CTAs/SM

// ---------------------------------------------------------------------------
// Scratch (static __device__ arrays; allocation-free kernel_launch)
// ---------------------------------------------------------------------------
__device__ int    g_cnt[NE];
__device__ int    g_ptok[NE * CAP];
__device__ float  g_pgate[NE * CAP];
__device__ __half g_X  [(size_t)NE * CAP * DIM];   // gathered tokens, fp16
__device__ __half g_W1h[(size_t)NE * DIM * HID];   // W1 fp16, layout [E][D][H]
__device__ __half g_W2h[(size_t)NE * HID * DIM];   // W2 fp16, layout [E][H][D]
__device__ __half g_Hb [(size_t)NE * CAP * HID];   // gelu(x@W1+b1), fp16

// ---------------------------------------------------------------------------
// PTX helpers (baseline compute_103-legal only: cp.async / ldmatrix / mma.sync)
// ---------------------------------------------------------------------------
__device__ __forceinline__ uint32_t smem_u32(const void* p) {
    uint32_t a;
    asm("{ .reg .u64 t; cvta.to.shared.u64 t, %1; cvt.u32.u64 %0, t; }"
        : "=r"(a) : "l"(p));
    return a;
}

__device__ __forceinline__ void cp16(uint32_t smaddr, const void* g) {
    asm volatile("cp.async.cg.shared.global [%0], [%1], 16;"
                 :: "r"(smaddr), "l"(g));
}
#define CP_COMMIT() asm volatile("cp.async.commit_group;" ::: "memory")
#define CP_WAIT(n)  asm volatile("cp.async.wait_group %0;" :: "n"(n) : "memory")

__device__ __forceinline__ void ldsm_x4(uint32_t* r, uint32_t addr) {
    asm volatile("ldmatrix.sync.aligned.m8n8.x4.shared.b16 {%0,%1,%2,%3}, [%4];"
                 : "=r"(r[0]), "=r"(r[1]), "=r"(r[2]), "=r"(r[3]) : "r"(addr));
}
__device__ __forceinline__ void ldsm_x4_t(uint32_t* r, uint32_t addr) {
    asm volatile("ldmatrix.sync.aligned.m8n8.x4.trans.shared.b16 {%0,%1,%2,%3}, [%4];"
                 : "=r"(r[0]), "=r"(r[1]), "=r"(r[2]), "=r"(r[3]) : "r"(addr));
}

__device__ __forceinline__ void mma16816(float* c, const uint32_t* a, const uint32_t* b) {
    asm volatile(
        "mma.sync.aligned.m16n8k16.row.col.f32.f16.f16.f32 "
        "{%0,%1,%2,%3}, {%4,%5,%6,%7}, {%8,%9}, {%0,%1,%2,%3};"
        : "+f"(c[0]), "+f"(c[1]), "+f"(c[2]), "+f"(c[3])
        : "r"(a[0]), "r"(a[1]), "r"(a[2]), "r"(a[3]), "r"(b[0]), "r"(b[1]));
}

// tanh-approximate GELU (JAX default): x * sigmoid(2u), u = 0.79788(x+0.044715x^3)
__device__ __forceinline__ float gelu_f(float v) {
    float u2 = 2.0f * 0.7978845608028654f * (v + 0.044715f * v * v * v);
    u2 = fminf(fmaxf(u2, -30.0f), 30.0f);
    float t = __expf(u2);
    return v * __fdividef(t, t + 1.0f);
}

// fp32x4 -> packed half2x2 convert helper
__device__ __forceinline__ uint2 cvt4h(float4 v) {
    __half2 a0 = __floats2half2_rn(v.x, v.y);
    __half2 a1 = __floats2half2_rn(v.z, v.w);
    uint2 u;
    u.x = *reinterpret_cast<unsigned*>(&a0);
    u.y = *reinterpret_cast<unsigned*>(&a1);
    return u;
}

// ---------------------------------------------------------------------------
// Kernel 1: zero expert counters (must precede router only)
// ---------------------------------------------------------------------------
__global__ void zero_cnt_kernel() {
    if (threadIdx.x < NE) g_cnt[threadIdx.x] = 0;
}

// ---------------------------------------------------------------------------
// Kernel 2 (merged prep): blocks [0, RBLK) = fused router+gather (one warp
// per token); blocks [RBLK, RBLK+CBLK) = W1 fp32->fp16 convert + zero `out`.
// Router (latency/atomic-bound) and convert (DRAM-bound) run concurrently.
// ---------------------------------------------------------------------------
#define RBLK (NTOK / 8)    // 1024 router blocks (256 thr = 8 warps)
#define CBLK 1024          // convert/zero blocks

__global__ void prep_kernel(const float* __restrict__ x,
                            const float* __restrict__ Wr,
                            const float* __restrict__ W1,
                            float* __restrict__ out) {
    if (blockIdx.x >= RBLK) {
        int b = blockIdx.x - RBLK;
        size_t stride = (size_t)CBLK * blockDim.x;
        // zero output (needed before GEMM2's atomics)
        size_t n4o = (size_t)NTOK * DIM / 4;
        float4 z = make_float4(0.f, 0.f, 0.f, 0.f);
        for (size_t i = (size_t)b * blockDim.x + threadIdx.x; i < n4o; i += stride)
            ((float4*)out)[i] = z;
        // convert W1 -> fp16
        size_t n4 = (size_t)NE * DIM * HID / 4;
        for (size_t i = (size_t)b * blockDim.x + threadIdx.x; i < n4; i += stride)
            ((uint2*)g_W1h)[i] = cvt4h(((const float4*)W1)[i]);
        return;
    }

    // ---- router + gather
    int gwarp = (blockIdx.x * blockDim.x + threadIdx.x) >> 5;
    int lane = threadIdx.x & 31;
    const float* xr = x + (size_t)gwarp * DIM;
    float a0 = 0, a1 = 0, a2 = 0, a3 = 0, a4 = 0, a5 = 0, a6 = 0, a7 = 0;
    for (int d = lane; d < DIM; d += 32) {
        float xv = xr[d];
        const float4* w = (const float4*)(Wr + (size_t)d * NE);
        float4 w0 = w[0], w1 = w[1];
        a0 += xv * w0.x; a1 += xv * w0.y; a2 += xv * w0.z; a3 += xv * w0.w;
        a4 += xv * w1.x; a5 += xv * w1.y; a6 += xv * w1.z; a7 += xv * w1.w;
    }
#pragma unroll
    for (int o = 16; o > 0; o >>= 1) {
        a0 += __shfl_xor_sync(0xffffffffu, a0, o);
        a1 += __shfl_xor_sync(0xffffffffu, a1, o);
        a2 += __shfl_xor_sync(0xffffffffu, a2, o);
        a3 += __shfl_xor_sync(0xffffffffu, a3, o);
        a4 += __shfl_xor_sync(0xffffffffu, a4, o);
        a5 += __shfl_xor_sync(0xffffffffu, a5, o);
        a6 += __shfl_xor_sync(0xffffffffu, a6, o);
        a7 += __shfl_xor_sync(0xffffffffu, a7, o);
    }
    int i1 = 0, i2 = 0, s1 = 0, s2 = 0;
    if (lane == 0) {
        float p[8] = {a0, a1, a2, a3, a4, a5, a6, a7};
        float m = p[0];
#pragma unroll
        for (int e = 1; e < 8; e++) m = fmaxf(m, p[e]);
        float s = 0.f;
#pragma unroll
        for (int e = 0; e < 8; e++) { p[e] = expf(p[e] - m); s += p[e]; }
        float inv = 1.0f / s;
#pragma unroll
        for (int e = 0; e < 8; e++) p[e] *= inv;
        float v1 = p[0]; i1 = 0;
#pragma unroll
        for (int e = 1; e < 8; e++) if (p[e] > v1) { v1 = p[e]; i1 = e; }
        float v2 = -1.0f; i2 = -1;
#pragma unroll
        for (int e = 0; e < 8; e++)
            if (e != i1 && p[e] > v2) { v2 = p[e]; i2 = e; }
        s1 = atomicAdd(&g_cnt[i1], 1);
        g_ptok[i1 * CAP + s1] = gwarp; g_pgate[i1 * CAP + s1] = v1;
        s2 = atomicAdd(&g_cnt[i2], 1);
        g_ptok[i2 * CAP + s2] = gwarp; g_pgate[i2 * CAP + s2] = v2;
    }
    i1 = __shfl_sync(0xffffffffu, i1, 0);
    i2 = __shfl_sync(0xffffffffu, i2, 0);
    s1 = __shfl_sync(0xffffffffu, s1, 0);
    s2 = __shfl_sync(0xffffffffu, s2, 0);

    unsigned* d1 = (unsigned*)(g_X + ((size_t)i1 * CAP + s1) * DIM);
    unsigned* d2 = (unsigned*)(g_X + ((size_t)i2 * CAP + s2) * DIM);
    const float2* xf2 = (const float2*)xr;
#pragma unroll
    for (int i = 0; i < 16; i++) {
        int j = lane + i * 32;               // half2 index, 512 per row
        float2 v = __ldg(&xf2[j]);
        __half2 h = __floats2half2_rn(v.x, v.y);
        unsigned u = *reinterpret_cast<unsigned*>(&h);
        d1[j] = u; d2[j] = u;
    }
}

// ---------------------------------------------------------------------------
// Kernel 3: fp16 mma.sync GEMM, 128x128x64 tiles, 2-stage smem double buffer
// + register fragment double buffer. 4 warps as 2(M) x 2(N); warp tile 64x64.
// mode 0: H = gelu(X @ W1 + b1); blockIdx.z==NE slice converts W2 -> fp16
//         (DRAM-streaming work hidden under the compute-bound GEMM).
// mode 1: out[tok] += gate*(H @ W2 + b2)
// ---------------------------------------------------------------------------
#define GSMEM_BYTES (2 * (ASTAGE + BSTAGE))   // 71680 B

__global__ void __launch_bounds__(128, 2)
moe_gemm_kernel(int mode, const float* __restrict__ bias, float* __restrict__ out,
                const float* __restrict__ W2src) {
    extern __shared__ char dyn_smem[];

    int e = blockIdx.z;
    if (e == NE) {                   // W2 convert slice (mode 0 launch only)
        size_t n4 = (size_t)NE * HID * DIM / 4;
        int nb = gridDim.x * gridDim.y;
        int bid = blockIdx.y * gridDim.x + blockIdx.x;
        size_t stride = (size_t)nb * blockDim.x;
        for (size_t i = (size_t)bid * blockDim.x + threadIdx.x; i < n4; i += stride)
            ((uint2*)g_W2h)[i] = cvt4h(((const float4*)W2src)[i]);
        return;
    }

    int cnt = g_cnt[e];
    int row0 = blockIdx.y * BM;
    if (row0 >= cnt) return;
    int valid = cnt - row0;
    int nb0 = blockIdx.x * BN;

    const __half* Ag; const __half* Bg;
    int lda, ldb, Kdim;
    if (mode == 0) {
        Ag = g_X   + (size_t)e * CAP * DIM + (size_t)row0 * DIM;  lda = DIM;
        Bg = g_W1h + (size_t)e * DIM * HID;                       ldb = HID;
        Kdim = DIM;
    } else {
        Ag = g_Hb  + (size_t)e * CAP * HID + (size_t)row0 * HID;  lda = HID;
        Bg = g_W2h + (size_t)e * HID * DIM;                       ldb = DIM;
        Kdim = HID;
    }

    int tid = threadIdx.x;
    int lane = tid & 31;
    int warp = tid >> 5;
    int wm = warp >> 1;              // 0..1  (M groups of 64)
    int wn = warp & 1;               // 0..1  (N groups of 64)

    // ---- smem layout: [A stage0][A stage1][B stage0][B stage1]
    uint32_t smemA = smem_u32(dyn_smem);
    uint32_t smemB = smemA + 2 * ASTAGE;

    uint32_t aaddr = smemA + (uint32_t)(((wm * 64 + (lane & 15)) * LDA + ((lane >> 4) << 3)) * 2);
    uint32_t bbase = smemB + (uint32_t)(((lane & 15) * LDB + wn * 64 + ((lane >> 4) << 3)) * 2);

    uint32_t adst = smemA + (uint32_t)((((tid >> 3)) * LDA + (tid & 7) * 8) * 2);
    uint32_t bdst = smemB + (uint32_t)((((tid >> 4)) * LDB + (tid & 15) * 8) * 2);
    const __half* asrcp = Ag + (size_t)(tid >> 3) * lda + (tid & 7) * 8;
    const __half* bsrcp = Bg + (size_t)(tid >> 4) * ldb + nb0 + (tid & 15) * 8;
    const int a16 = 16 * lda;        // 16-row global stride (halves)
    const int b8  = 8 * ldb;         // 8-row global stride (halves)

    float acc[4][8][4];
#pragma unroll
    for (int mi = 0; mi < 4; mi++)
#pragma unroll
        for (int nj = 0; nj < 8; nj++)
#pragma unroll
            for (int q = 0; q < 4; q++) acc[mi][nj][q] = 0.f;

    auto load_stage = [&](uint32_t aoff, uint32_t boff) {
#pragma unroll
        for (int p = 0; p < 8; p++)
            cp16(adst + aoff + p * (16 * LDA * 2), asrcp + (size_t)p * a16);
#pragma unroll
        for (int p = 0; p < 8; p++)
            cp16(bdst + boff + p * (8 * LDB * 2), bsrcp + (size_t)p * b8);
        CP_COMMIT();
        asrcp += BK;
        bsrcp += (size_t)BK * ldb;
    };

    // register fragment double buffers
    uint32_t af[2][4][4];
    uint32_t bf[2][8][2];
    auto frag_load = [&](int buf, uint32_t aA, uint32_t bA, int ks) {
        const uint32_t ksa = ks * 32;              // 16 halves
        const uint32_t ksb = ks * 16 * LDB * 2;    // 16 rows
#pragma unroll
        for (int mi = 0; mi < 4; mi++)
            ldsm_x4(af[buf][mi], aA + ksa + mi * (16 * LDA * 2));
#pragma unroll
        for (int j = 0; j < 4; j++) {
            uint32_t r4[4];
            ldsm_x4_t(r4, bA + ksb + j * 32);
            bf[buf][2 * j][0] = r4[0]; bf[buf][2 * j][1] = r4[1];
            bf[buf][2 * j + 1][0] = r4[2]; bf[buf][2 * j + 1][1] = r4[3];
        }
    };

    int nk = Kdim / BK;              // 16 (GEMM1) or 64 (GEMM2)
    load_stage(0, 0);

    uint32_t consA = 0, consB = 0;
    uint32_t prodA = ASTAGE, prodB = BSTAGE;
    for (int kt = 0; kt < nk; kt++) {
        CP_WAIT(0);
        __syncthreads();
        if (kt + 1 < nk) {
            load_stage(prodA, prodB);      // overlaps this kt's compute
            prodA ^= ASTAGE; prodB ^= BSTAGE;
        }

        uint32_t aA = aaddr + consA;
        uint32_t bA = bbase + consB;

        frag_load(0, aA, bA, 0);
#pragma unroll
        for (int ks = 0; ks < 4; ks++) {
            int cb = ks & 1;
            if (ks < 3) frag_load(cb ^ 1, aA, bA, ks + 1);  // hide under HMMAs
#pragma unroll
            for (int mi = 0; mi < 4; mi++)
#pragma unroll
                for (int nj = 0; nj < 8; nj++)
                    mma16816(acc[mi][nj], af[cb][mi], bf[cb][nj]);
        }
        consA ^= ASTAGE; consB ^= BSTAGE;
    }

    // --- Epilogue. acc[mi][nj]: rows wm*64+mi*16+{lane/4,+8}, cols wn*64+nj*8+(lane%4)*2+{0,1}
    if (mode == 0) {
        const float* bp = bias + (size_t)e * HID + nb0;
#pragma unroll
        for (int mi = 0; mi < 4; mi++) {
            int rb = wm * 64 + mi * 16 + (lane >> 2);
#pragma unroll
            for (int hr = 0; hr < 2; hr++) {
                int r = rb + hr * 8;
                if (r < valid) {
                    size_t rowoff = ((size_t)e * CAP + row0 + r) * HID + nb0;
#pragma unroll
                    for (int nj = 0; nj < 8; nj++) {
                        int colc = wn * 64 + nj * 8 + ((lane & 3) << 1);
                        float v0 = acc[mi][nj][hr * 2 + 0] + bp[colc];
                        float v1 = acc[mi][nj][hr * 2 + 1] + bp[colc + 1];
                        __half2 h2 = __floats2half2_rn(gelu_f(v0), gelu_f(v1));
                        *(__half2*)(g_Hb + rowoff + colc) = h2;
                    }
                }
            }
        }
    } else {
        const float* bp = bias + (size_t)e * DIM + nb0;
#pragma unroll
        for (int mi = 0; mi < 4; mi++) {
            int rb = wm * 64 + mi * 16 + (lane >> 2);
#pragma unroll
            for (int hr = 0; hr < 2; hr++) {
                int r = rb + hr * 8;
                if (r < valid) {
                    int t = g_ptok[e * CAP + row0 + r];
                    float gate = g_pgate[e * CAP + row0 + r];
                    float* orow = out + (size_t)t * DIM + nb0;
#pragma unroll
                    for (int nj = 0; nj < 8; nj++) {
                        int colc = wn * 64 + nj * 8 + ((lane & 3) << 1);
                        float v0 = acc[mi][nj][hr * 2 + 0] + bp[colc];
                        float v1 = acc[mi][nj][hr * 2 + 1] + bp[colc + 1];
                        atomicAdd(orow + colc,     gate * v0);
                        atomicAdd(orow + colc + 1, gate * v1);
                    }
                }
            }
        }
    }
}

// ---------------------------------------------------------------------------
// Launch
// ---------------------------------------------------------------------------
extern "C" void kernel_launch(void* const* d_in, const int* in_sizes, int n_in,
                              void* d_out, int out_size) {
    const float* x  = (const float*)d_in[0];
    const float* Wr = (const float*)d_in[1];
    const float* W1 = (const float*)d_in[2];
    const float* b1 = (const float*)d_in[3];
    const float* W2 = (const float*)d_in[4];
    const float* b2 = (const float*)d_in[5];
    float* out = (float*)d_out;

    static int smem_set = 0;
    if (!smem_set) {
        cudaFuncSetAttribute(moe_gemm_kernel,
                             cudaFuncAttributeMaxDynamicSharedMemorySize,
                             GSMEM_BYTES);
        smem_set = 1;
    }

    // 1. zero expert counters
    zero_cnt_kernel<<<1, 32>>>();
    // 2. merged prep: router+gather || W1 convert + out zeroing
    prep_kernel<<<RBLK + CBLK, 256>>>(x, Wr, W1, out);
    // 3. GEMM1 (+ W2 convert hidden in extra z-slice)
    moe_gemm_kernel<<<dim3(HID / BN, CAP / BM, NE + 1), 128, GSMEM_BYTES>>>(0, b1, nullptr, W2);
    // 4. GEMM2
    moe_gemm_kernel<<<dim3(DIM / BN, CAP / BM, NE), 128, GSMEM_BYTES>>>(1, b2, out, nullptr);
}

// round 12
// speedup vs baseline: 1.0887x; 1.0887x over previous
#include <cuda_runtime.h>
#include <cuda_fp16.h>
#include <cstdint>

// ---------------------------------------------------------------------------
// Problem dims (fixed by the dataset)
// ---------------------------------------------------------------------------
#define NTOK 8192          // B*S tokens
#define DIM  1024          // model dim
#define HID  4096          // hidden dim
#define NE   8             // experts
#define CAP  8192          // per-expert token capacity (max possible)

#define BM 128
#define BN 128
#define BK 64
#define LDA (BK + 8)       // 72 halves (144B rows; conflict-free for ldmatrix)
#define LDB (BN + 8)       // 136 halves (272B rows; conflict-free for ldmatrix)
#define ASTAGE (BM * LDA * 2)      // 18432 B per A stage
#define BSTAGE (BK * LDB * 2)      // 17408 B per B stage
// 2 stages: (18432+17408)*2 = 71680 B per CTA -> 2 CTAs/SM

// ---------------------------------------------------------------------------
// Scratch (static __device__ arrays; allocation-free kernel_launch)
// ---------------------------------------------------------------------------
__device__ int    g_cnt[NE];
__device__ int    g_ptok[NE * CAP];
__device__ float  g_pgate[NE * CAP];
__device__ __half g_X  [(size_t)NE * CAP * DIM];   // gathered tokens, fp16
__device__ __half g_W1h[(size_t)NE * DIM * HID];   // W1 fp16, layout [E][D][H]
__device__ __half g_W2h[(size_t)NE * HID * DIM];   // W2 fp16, layout [E][H][D]
__device__ __half g_Hb [(size_t)NE * CAP * HID];   // gelu(x@W1+b1), fp16

// ---------------------------------------------------------------------------
// PTX helpers (baseline compute_103-legal only: cp.async / ldmatrix / mma.sync)
// ---------------------------------------------------------------------------
__device__ __forceinline__ uint32_t smem_u32(const void* p) {
    uint32_t a;
    asm("{ .reg .u64 t; cvta.to.shared.u64 t, %1; cvt.u32.u64 %0, t; }"
        : "=r"(a) : "l"(p));
    return a;
}

__device__ __forceinline__ void cp16(uint32_t smaddr, const void* g) {
    asm volatile("cp.async.cg.shared.global [%0], [%1], 16;"
                 :: "r"(smaddr), "l"(g));
}
#define CP_COMMIT() asm volatile("cp.async.commit_group;" ::: "memory")
#define CP_WAIT(n)  asm volatile("cp.async.wait_group %0;" :: "n"(n) : "memory")

__device__ __forceinline__ void ldsm_x4(uint32_t* r, uint32_t addr) {
    asm volatile("ldmatrix.sync.aligned.m8n8.x4.shared.b16 {%0,%1,%2,%3}, [%4];"
                 : "=r"(r[0]), "=r"(r[1]), "=r"(r[2]), "=r"(r[3]) : "r"(addr));
}
__device__ __forceinline__ void ldsm_x4_t(uint32_t* r, uint32_t addr) {
    asm volatile("ldmatrix.sync.aligned.m8n8.x4.trans.shared.b16 {%0,%1,%2,%3}, [%4];"
                 : "=r"(r[0]), "=r"(r[1]), "=r"(r[2]), "=r"(r[3]) : "r"(addr));
}

__device__ __forceinline__ void mma16816(float* c, const uint32_t* a, const uint32_t* b) {
    asm volatile(
        "mma.sync.aligned.m16n8k16.row.col.f32.f16.f16.f32 "
        "{%0,%1,%2,%3}, {%4,%5,%6,%7}, {%8,%9}, {%0,%1,%2,%3};"
        : "+f"(c[0]), "+f"(c[1]), "+f"(c[2]), "+f"(c[3])
        : "r"(a[0]), "r"(a[1]), "r"(a[2]), "r"(a[3]), "r"(b[0]), "r"(b[1]));
}

// tanh-approximate GELU (JAX default): x * sigmoid(2u), u = 0.79788(x+0.044715x^3)
__device__ __forceinline__ float gelu_f(float v) {
    float u2 = 2.0f * 0.7978845608028654f * (v + 0.044715f * v * v * v);
    u2 = fminf(fmaxf(u2, -30.0f), 30.0f);
    float t = __expf(u2);
    return v * __fdividef(t, t + 1.0f);
}

// fp32x4 -> packed half2x2 convert helper
__device__ __forceinline__ uint2 cvt4h(float4 v) {
    __half2 a0 = __floats2half2_rn(v.x, v.y);
    __half2 a1 = __floats2half2_rn(v.z, v.w);
    uint2 u;
    u.x = *reinterpret_cast<unsigned*>(&a0);
    u.y = *reinterpret_cast<unsigned*>(&a1);
    return u;
}

// ---------------------------------------------------------------------------
// Kernel 1: zero expert counters (must precede router only)
// ---------------------------------------------------------------------------
__global__ void zero_cnt_kernel() {
    if (threadIdx.x < NE) g_cnt[threadIdx.x] = 0;
}

// ---------------------------------------------------------------------------
// Kernel 2 (merged prep): blocks [0, RBLK) = fused router+gather (one warp
// per token); blocks [RBLK, RBLK+CBLK) = zero `out` + convert W1 AND W2 to
// fp16. Router (latency/atomic-bound) and converts (DRAM-bound) run
// concurrently on disjoint S,M resources.
// ---------------------------------------------------------------------------
#define RBLK (NTOK / 8)    // 1024 router blocks (256 thr = 8 warps)
#define CBLK 1024          // convert/zero blocks

__global__ void prep_kernel(const float* __restrict__ x,
                            const float* __restrict__ Wr,
                            const float* __restrict__ W1,
                            const float* __restrict__ W2,
                            float* __restrict__ out) {
    if (blockIdx.x >= RBLK) {
        int b = blockIdx.x - RBLK;
        size_t stride = (size_t)CBLK * blockDim.x;
        // zero output (needed before GEMM2's atomics)
        size_t n4o = (size_t)NTOK * DIM / 4;
        float4 z = make_float4(0.f, 0.f, 0.f, 0.f);
        for (size_t i = (size_t)b * blockDim.x + threadIdx.x; i < n4o; i += stride)
            ((float4*)out)[i] = z;
        // convert W1, W2 -> fp16 (same element count; one fused loop)
        size_t n4 = (size_t)NE * DIM * HID / 4;
        for (size_t i = (size_t)b * blockDim.x + threadIdx.x; i < n4; i += stride) {
            ((uint2*)g_W1h)[i] = cvt4h(((const float4*)W1)[i]);
            ((uint2*)g_W2h)[i] = cvt4h(((const float4*)W2)[i]);
        }
        return;
    }

    // ---- router + gather
    int gwarp = (blockIdx.x * blockDim.x + threadIdx.x) >> 5;
    int lane = threadIdx.x & 31;
    const float* xr = x + (size_t)gwarp * DIM;
    float a0 = 0, a1 = 0, a2 = 0, a3 = 0, a4 = 0, a5 = 0, a6 = 0, a7 = 0;
    for (int d = lane; d < DIM; d += 32) {
        float xv = xr[d];
        const float4* w = (const float4*)(Wr + (size_t)d * NE);
        float4 w0 = w[0], w1 = w[1];
        a0 += xv * w0.x; a1 += xv * w0.y; a2 += xv * w0.z; a3 += xv * w0.w;
        a4 += xv * w1.x; a5 += xv * w1.y; a6 += xv * w1.z; a7 += xv * w1.w;
    }
#pragma unroll
    for (int o = 16; o > 0; o >>= 1) {
        a0 += __shfl_xor_sync(0xffffffffu, a0, o);
        a1 += __shfl_xor_sync(0xffffffffu, a1, o);
        a2 += __shfl_xor_sync(0xffffffffu, a2, o);
        a3 += __shfl_xor_sync(0xffffffffu, a3, o);
        a4 += __shfl_xor_sync(0xffffffffu, a4, o);
        a5 += __shfl_xor_sync(0xffffffffu, a5, o);
        a6 += __shfl_xor_sync(0xffffffffu, a6, o);
        a7 += __shfl_xor_sync(0xffffffffu, a7, o);
    }
    int i1 = 0, i2 = 0, s1 = 0, s2 = 0;
    if (lane == 0) {
        float p[8] = {a0, a1, a2, a3, a4, a5, a6, a7};
        float m = p[0];
#pragma unroll
        for (int e = 1; e < 8; e++) m = fmaxf(m, p[e]);
        float s = 0.f;
#pragma unroll
        for (int e = 0; e < 8; e++) { p[e] = expf(p[e] - m); s += p[e]; }
        float inv = 1.0f / s;
#pragma unroll
        for (int e = 0; e < 8; e++) p[e] *= inv;
        float v1 = p[0]; i1 = 0;
#pragma unroll
        for (int e = 1; e < 8; e++) if (p[e] > v1) { v1 = p[e]; i1 = e; }
        float v2 = -1.0f; i2 = -1;
#pragma unroll
        for (int e = 0; e < 8; e++)
            if (e != i1 && p[e] > v2) { v2 = p[e]; i2 = e; }
        s1 = atomicAdd(&g_cnt[i1], 1);
        g_ptok[i1 * CAP + s1] = gwarp; g_pgate[i1 * CAP + s1] = v1;
        s2 = atomicAdd(&g_cnt[i2], 1);
        g_ptok[i2 * CAP + s2] = gwarp; g_pgate[i2 * CAP + s2] = v2;
    }
    i1 = __shfl_sync(0xffffffffu, i1, 0);
    i2 = __shfl_sync(0xffffffffu, i2, 0);
    s1 = __shfl_sync(0xffffffffu, s1, 0);
    s2 = __shfl_sync(0xffffffffu, s2, 0);

    unsigned* d1 = (unsigned*)(g_X + ((size_t)i1 * CAP + s1) * DIM);
    unsigned* d2 = (unsigned*)(g_X + ((size_t)i2 * CAP + s2) * DIM);
    const float2* xf2 = (const float2*)xr;
#pragma unroll
    for (int i = 0; i < 16; i++) {
        int j = lane + i * 32;               // half2 index, 512 per row
        float2 v = __ldg(&xf2[j]);
        __half2 h = __floats2half2_rn(v.x, v.y);
        unsigned u = *reinterpret_cast<unsigned*>(&h);
        d1[j] = u; d2[j] = u;
    }
}

// ---------------------------------------------------------------------------
// Kernel 3: fp16 mma.sync GEMM, 128x128x64 tiles, 2-stage smem double buffer
// + register fragment double buffer. 4 warps as 2(M) x 2(N); warp tile 64x64.
// mode 0: H = gelu(X @ W1 + b1)        (A = g_X [rows,D], B = W1h [D,H])
// mode 1: out[tok] += gate*(H @ W2+b2) (A = g_Hb [rows,H], B = W2h [H,D])
// ---------------------------------------------------------------------------
#define GSMEM_BYTES (2 * (ASTAGE + BSTAGE))   // 71680 B

__global__ void __launch_bounds__(128, 2)
moe_gemm_kernel(int mode, const float* __restrict__ bias, float* __restrict__ out) {
    extern __shared__ char dyn_smem[];

    int e = blockIdx.z;
    int cnt = g_cnt[e];
    int row0 = blockIdx.y * BM;
    if (row0 >= cnt) return;
    int valid = cnt - row0;
    int nb0 = blockIdx.x * BN;

    const __half* Ag; const __half* Bg;
    int lda, ldb, Kdim;
    if (mode == 0) {
        Ag = g_X   + (size_t)e * CAP * DIM + (size_t)row0 * DIM;  lda = DIM;
        Bg = g_W1h + (size_t)e * DIM * HID;                       ldb = HID;
        Kdim = DIM;
    } else {
        Ag = g_Hb  + (size_t)e * CAP * HID + (size_t)row0 * HID;  lda = HID;
        Bg = g_W2h + (size_t)e * HID * DIM;                       ldb = DIM;
        Kdim = HID;
    }

    int tid = threadIdx.x;
    int lane = tid & 31;
    int warp = tid >> 5;
    int wm = warp >> 1;              // 0..1  (M groups of 64)
    int wn = warp & 1;               // 0..1  (N groups of 64)

    // ---- smem layout: [A stage0][A stage1][B stage0][B stage1]
    uint32_t smemA = smem_u32(dyn_smem);
    uint32_t smemB = smemA + 2 * ASTAGE;

    uint32_t aaddr = smemA + (uint32_t)(((wm * 64 + (lane & 15)) * LDA + ((lane >> 4) << 3)) * 2);
    uint32_t bbase = smemB + (uint32_t)(((lane & 15) * LDB + wn * 64 + ((lane >> 4) << 3)) * 2);

    uint32_t adst = smemA + (uint32_t)((((tid >> 3)) * LDA + (tid & 7) * 8) * 2);
    uint32_t bdst = smemB + (uint32_t)((((tid >> 4)) * LDB + (tid & 15) * 8) * 2);
    const __half* asrcp = Ag + (size_t)(tid >> 3) * lda + (tid & 7) * 8;
    const __half* bsrcp = Bg + (size_t)(tid >> 4) * ldb + nb0 + (tid & 15) * 8;
    const int a16 = 16 * lda;        // 16-row global stride (halves)
    const int b8  = 8 * ldb;         // 8-row global stride (halves)

    float acc[4][8][4];
#pragma unroll
    for (int mi = 0; mi < 4; mi++)
#pragma unroll
        for (int nj = 0; nj < 8; nj++)
#pragma unroll
            for (int q = 0; q < 4; q++) acc[mi][nj][q] = 0.f;

    auto load_stage = [&](uint32_t aoff, uint32_t boff) {
#pragma unroll
        for (int p = 0; p < 8; p++)
            cp16(adst + aoff + p * (16 * LDA * 2), asrcp + (size_t)p * a16);
#pragma unroll
        for (int p = 0; p < 8; p++)
            cp16(bdst + boff + p * (8 * LDB * 2), bsrcp + (size_t)p * b8);
        CP_COMMIT();
        asrcp += BK;
        bsrcp += (size_t)BK * ldb;
    };

    // register fragment double buffers
    uint32_t af[2][4][4];
    uint32_t bf[2][8][2];
    auto frag_load = [&](int buf, uint32_t aA, uint32_t bA, int ks) {
        const uint32_t ksa = ks * 32;              // 16 halves
        const uint32_t ksb = ks * 16 * LDB * 2;    // 16 rows
#pragma unroll
        for (int mi = 0; mi < 4; mi++)
            ldsm_x4(af[buf][mi], aA + ksa + mi * (16 * LDA * 2));
#pragma unroll
        for (int j = 0; j < 4; j++) {
            uint32_t r4[4];
            ldsm_x4_t(r4, bA + ksb + j * 32);
            bf[buf][2 * j][0] = r4[0]; bf[buf][2 * j][1] = r4[1];
            bf[buf][2 * j + 1][0] = r4[2]; bf[buf][2 * j + 1][1] = r4[3];
        }
    };

    int nk = Kdim / BK;              // 16 (GEMM1) or 64 (GEMM2)
    load_stage(0, 0);

    uint32_t consA = 0, consB = 0;
    uint32_t prodA = ASTAGE, prodB = BSTAGE;
    for (int kt = 0; kt < nk; kt++) {
        CP_WAIT(0);
        __syncthreads();
        if (kt + 1 < nk) {
            load_stage(prodA, prodB);      // overlaps this kt's compute
            prodA ^= ASTAGE; prodB ^= BSTAGE;
        }

        uint32_t aA = aaddr + consA;
        uint32_t bA = bbase + consB;

        frag_load(0, aA, bA, 0);
#pragma unroll
        for (int ks = 0; ks < 4; ks++) {
            int cb = ks & 1;
            if (ks < 3) frag_load(cb ^ 1, aA, bA, ks + 1);  // hide under HMMAs
#pragma unroll
            for (int mi = 0; mi < 4; mi++)
#pragma unroll
                for (int nj = 0; nj < 8; nj++)
                    mma16816(acc[mi][nj], af[cb][mi], bf[cb][nj]);
        }
        consA ^= ASTAGE; consB ^= BSTAGE;
    }

    // --- Epilogue. acc[mi][nj]: rows wm*64+mi*16+{lane/4,+8}, cols wn*64+nj*8+(lane%4)*2+{0,1}
    if (mode == 0) {
        const float* bp = bias + (size_t)e * HID + nb0;
#pragma unroll
        for (int mi = 0; mi < 4; mi++) {
            int rb = wm * 64 + mi * 16 + (lane >> 2);
#pragma unroll
            for (int hr = 0; hr < 2; hr++) {
                int r = rb + hr * 8;
                if (r < valid) {
                    size_t rowoff = ((size_t)e * CAP + row0 + r) * HID + nb0;
#pragma unroll
                    for (int nj = 0; nj < 8; nj++) {
                        int colc = wn * 64 + nj * 8 + ((lane & 3) << 1);
                        float v0 = acc[mi][nj][hr * 2 + 0] + bp[colc];
                        float v1 = acc[mi][nj][hr * 2 + 1] + bp[colc + 1];
                        __half2 h2 = __floats2half2_rn(gelu_f(v0), gelu_f(v1));
                        *(__half2*)(g_Hb + rowoff + colc) = h2;
                    }
                }
            }
        }
    } else {
        const float* bp = bias + (size_t)e * DIM + nb0;
#pragma unroll
        for (int mi = 0; mi < 4; mi++) {
            int rb = wm * 64 + mi * 16 + (lane >> 2);
#pragma unroll
            for (int hr = 0; hr < 2; hr++) {
                int r = rb + hr * 8;
                if (r < valid) {
                    int t = g_ptok[e * CAP + row0 + r];
                    float gate = g_pgate[e * CAP + row0 + r];
                    float* orow = out + (size_t)t * DIM + nb0;
#pragma unroll
                    for (int nj = 0; nj < 8; nj++) {
                        int colc = wn * 64 + nj * 8 + ((lane & 3) << 1);
                        float v0 = acc[mi][nj][hr * 2 + 0] + bp[colc];
                        float v1 = acc[mi][nj][hr * 2 + 1] + bp[colc + 1];
                        atomicAdd(orow + colc,     gate * v0);
                        atomicAdd(orow + colc + 1, gate * v1);
                    }
                }
            }
        }
    }
}

// ---------------------------------------------------------------------------
// Launch
// ---------------------------------------------------------------------------
extern "C" void kernel_launch(void* const* d_in, const int* in_sizes, int n_in,
                              void* d_out, int out_size) {
    const float* x  = (const float*)d_in[0];
    const float* Wr = (const float*)d_in[1];
    const float* W1 = (const float*)d_in[2];
    const float* b1 = (const float*)d_in[3];
    const float* W2 = (const float*)d_in[4];
    const float* b2 = (const float*)d_in[5];
    float* out = (float*)d_out;

    static int smem_set = 0;
    if (!smem_set) {
        cudaFuncSetAttribute(moe_gemm_kernel,
                             cudaFuncAttributeMaxDynamicSharedMemorySize,
                             GSMEM_BYTES);
        smem_set = 1;
    }

    // 1. zero expert counters
    zero_cnt_kernel<<<1, 32>>>();
    // 2. merged prep: router+gather || (zero out + W1/W2 convert)
    prep_kernel<<<RBLK + CBLK, 256>>>(x, Wr, W1, W2, out);
    // 3. GEMM1: H = gelu(X @ W1 + b1)
    moe_gemm_kernel<<<dim3(HID / BN, CAP / BM, NE), 128, GSMEM_BYTES>>>(0, b1, nullptr);
    // 4. GEMM2: out += gate * (H @ W2 + b2)
    moe_gemm_kernel<<<dim3(DIM / BN, CAP / BM, NE), 128, GSMEM_BYTES>>>(1, b2, out);
}

// round 13
// speedup vs baseline: 1.0927x; 1.0036x over previous
#include <cuda_runtime.h>
#include <cuda_fp16.h>
#include <cstdint>

// ---------------------------------------------------------------------------
// Problem dims (fixed by the dataset)
// ---------------------------------------------------------------------------
#define NTOK 8192          // B*S tokens
#define DIM  1024          // model dim
#define HID  4096          // hidden dim
#define NE   8             // experts
#define CAP  8192          // per-expert token capacity (max possible)

#define BM 128
#define BN 128
#define BK 64
#define LDA (BK + 8)       // 72 halves (144B rows; conflict-free for ldmatrix)
#define LDB (BN + 8)       // 136 halves (272B rows; conflict-free for ldmatrix)
#define ASTAGE (BM * LDA * 2)      // 18432 B per A stage
#define BSTAGE (BK * LDB * 2)      // 17408 B per B stage
// 2 stages: (18432+17408)*2 = 71680 B per CTA -> 2 CTAs/SM

// ---------------------------------------------------------------------------
// Scratch (static __device__ arrays; allocation-free kernel_launch)
// ---------------------------------------------------------------------------
__device__ int    g_cnt[NE];
__device__ int    g_ptok[NE * CAP];
__device__ float  g_pgate[NE * CAP];
__device__ __half g_X  [(size_t)NE * CAP * DIM];   // gathered tokens, fp16
__device__ __half g_W1h[(size_t)NE * DIM * HID];   // W1 fp16, layout [E][D][H]
__device__ __half g_W2h[(size_t)NE * HID * DIM];   // W2 fp16, layout [E][H][D]
__device__ __half g_Hb [(size_t)NE * CAP * HID];   // gelu(x@W1+b1), fp16

// ---------------------------------------------------------------------------
// PTX helpers (baseline compute_103-legal only: cp.async / ldmatrix / mma.sync)
// ---------------------------------------------------------------------------
__device__ __forceinline__ uint32_t smem_u32(const void* p) {
    uint32_t a;
    asm("{ .reg .u64 t; cvta.to.shared.u64 t, %1; cvt.u32.u64 %0, t; }"
        : "=r"(a) : "l"(p));
    return a;
}

__device__ __forceinline__ void cp16(uint32_t smaddr, const void* g) {
    asm volatile("cp.async.cg.shared.global [%0], [%1], 16;"
                 :: "r"(smaddr), "l"(g));
}
#define CP_COMMIT() asm volatile("cp.async.commit_group;" ::: "memory")
#define CP_WAIT(n)  asm volatile("cp.async.wait_group %0;" :: "n"(n) : "memory")

__device__ __forceinline__ void ldsm_x4(uint32_t* r, uint32_t addr) {
    asm volatile("ldmatrix.sync.aligned.m8n8.x4.shared.b16 {%0,%1,%2,%3}, [%4];"
                 : "=r"(r[0]), "=r"(r[1]), "=r"(r[2]), "=r"(r[3]) : "r"(addr));
}
__device__ __forceinline__ void ldsm_x4_t(uint32_t* r, uint32_t addr) {
    asm volatile("ldmatrix.sync.aligned.m8n8.x4.trans.shared.b16 {%0,%1,%2,%3}, [%4];"
                 : "=r"(r[0]), "=r"(r[1]), "=r"(r[2]), "=r"(r[3]) : "r"(addr));
}

__device__ __forceinline__ void mma16816(float* c, const uint32_t* a, const uint32_t* b) {
    asm volatile(
        "mma.sync.aligned.m16n8k16.row.col.f32.f16.f16.f32 "
        "{%0,%1,%2,%3}, {%4,%5,%6,%7}, {%8,%9}, {%0,%1,%2,%3};"
        : "+f"(c[0]), "+f"(c[1]), "+f"(c[2]), "+f"(c[3])
        : "r"(a[0]), "r"(a[1]), "r"(a[2]), "r"(a[3]), "r"(b[0]), "r"(b[1]));
}

// tanh-approximate GELU (JAX default): x * sigmoid(2u), u = 0.79788(x+0.044715x^3)
__device__ __forceinline__ float gelu_f(float v) {
    float u2 = 2.0f * 0.7978845608028654f * (v + 0.044715f * v * v * v);
    u2 = fminf(fmaxf(u2, -30.0f), 30.0f);
    float t = __expf(u2);
    return v * __fdividef(t, t + 1.0f);
}

// fp32x4 -> packed half2x2 convert helper
__device__ __forceinline__ uint2 cvt4h(float4 v) {
    __half2 a0 = __floats2half2_rn(v.x, v.y);
    __half2 a1 = __floats2half2_rn(v.z, v.w);
    uint2 u;
    u.x = *reinterpret_cast<unsigned*>(&a0);
    u.y = *reinterpret_cast<unsigned*>(&a1);
    return u;
}

// ---------------------------------------------------------------------------
// Kernel 1: zero expert counters (must precede router only)
// ---------------------------------------------------------------------------
__global__ void zero_cnt_kernel() {
    if (threadIdx.x < NE) g_cnt[threadIdx.x] = 0;
}

// ---------------------------------------------------------------------------
// Kernel 2 (merged prep): blocks [0, RBLK) = fused router+gather (one warp
// per token); blocks [RBLK, RBLK+CBLK) = zero `out` + convert W1 -> fp16.
// (W2 convert is deferred: it rides inside GEMM1's CTAs as tail work.)
// ---------------------------------------------------------------------------
#define RBLK (NTOK / 8)    // 1024 router blocks (256 thr = 8 warps)
#define CBLK 1024          // convert/zero blocks

__global__ void prep_kernel(const float* __restrict__ x,
                            const float* __restrict__ Wr,
                            const float* __restrict__ W1,
                            float* __restrict__ out) {
    if (blockIdx.x >= RBLK) {
        int b = blockIdx.x - RBLK;
        size_t stride = (size_t)CBLK * blockDim.x;
        // zero output (needed before GEMM2's atomics)
        size_t n4o = (size_t)NTOK * DIM / 4;
        float4 z = make_float4(0.f, 0.f, 0.f, 0.f);
        for (size_t i = (size_t)b * blockDim.x + threadIdx.x; i < n4o; i += stride)
            ((float4*)out)[i] = z;
        // convert W1 -> fp16
        size_t n4 = (size_t)NE * DIM * HID / 4;
        for (size_t i = (size_t)b * blockDim.x + threadIdx.x; i < n4; i += stride)
            ((uint2*)g_W1h)[i] = cvt4h(((const float4*)W1)[i]);
        return;
    }

    // ---- router + gather
    int gwarp = (blockIdx.x * blockDim.x + threadIdx.x) >> 5;
    int lane = threadIdx.x & 31;
    const float* xr = x + (size_t)gwarp * DIM;
    float a0 = 0, a1 = 0, a2 = 0, a3 = 0, a4 = 0, a5 = 0, a6 = 0, a7 = 0;
    for (int d = lane; d < DIM; d += 32) {
        float xv = xr[d];
        const float4* w = (const float4*)(Wr + (size_t)d * NE);
        float4 w0 = w[0], w1 = w[1];
        a0 += xv * w0.x; a1 += xv * w0.y; a2 += xv * w0.z; a3 += xv * w0.w;
        a4 += xv * w1.x; a5 += xv * w1.y; a6 += xv * w1.z; a7 += xv * w1.w;
    }
#pragma unroll
    for (int o = 16; o > 0; o >>= 1) {
        a0 += __shfl_xor_sync(0xffffffffu, a0, o);
        a1 += __shfl_xor_sync(0xffffffffu, a1, o);
        a2 += __shfl_xor_sync(0xffffffffu, a2, o);
        a3 += __shfl_xor_sync(0xffffffffu, a3, o);
        a4 += __shfl_xor_sync(0xffffffffu, a4, o);
        a5 += __shfl_xor_sync(0xffffffffu, a5, o);
        a6 += __shfl_xor_sync(0xffffffffu, a6, o);
        a7 += __shfl_xor_sync(0xffffffffu, a7, o);
    }
    int i1 = 0, i2 = 0, s1 = 0, s2 = 0;
    if (lane == 0) {
        float p[8] = {a0, a1, a2, a3, a4, a5, a6, a7};
        float m = p[0];
#pragma unroll
        for (int e = 1; e < 8; e++) m = fmaxf(m, p[e]);
        float s = 0.f;
#pragma unroll
        for (int e = 0; e < 8; e++) { p[e] = expf(p[e] - m); s += p[e]; }
        float inv = 1.0f / s;
#pragma unroll
        for (int e = 0; e < 8; e++) p[e] *= inv;
        float v1 = p[0]; i1 = 0;
#pragma unroll
        for (int e = 1; e < 8; e++) if (p[e] > v1) { v1 = p[e]; i1 = e; }
        float v2 = -1.0f; i2 = -1;
#pragma unroll
        for (int e = 0; e < 8; e++)
            if (e != i1 && p[e] > v2) { v2 = p[e]; i2 = e; }
        s1 = atomicAdd(&g_cnt[i1], 1);
        g_ptok[i1 * CAP + s1] = gwarp; g_pgate[i1 * CAP + s1] = v1;
        s2 = atomicAdd(&g_cnt[i2], 1);
        g_ptok[i2 * CAP + s2] = gwarp; g_pgate[i2 * CAP + s2] = v2;
    }
    i1 = __shfl_sync(0xffffffffu, i1, 0);
    i2 = __shfl_sync(0xffffffffu, i2, 0);
    s1 = __shfl_sync(0xffffffffu, s1, 0);
    s2 = __shfl_sync(0xffffffffu, s2, 0);

    unsigned* d1 = (unsigned*)(g_X + ((size_t)i1 * CAP + s1) * DIM);
    unsigned* d2 = (unsigned*)(g_X + ((size_t)i2 * CAP + s2) * DIM);
    const float2* xf2 = (const float2*)xr;
#pragma unroll
    for (int i = 0; i < 16; i++) {
        int j = lane + i * 32;               // half2 index, 512 per row
        float2 v = __ldg(&xf2[j]);
        __half2 h = __floats2half2_rn(v.x, v.y);
        unsigned u = *reinterpret_cast<unsigned*>(&h);
        d1[j] = u; d2[j] = u;
    }
}

// ---------------------------------------------------------------------------
// Kernel 3: fp16 mma.sync GEMM, 128x128x64 tiles, 2-stage smem double buffer
// + register fragment double buffer. 4 warps as 2(M) x 2(N); warp tile 64x64.
// mode 0: H = gelu(X @ W1 + b1); additionally EVERY mode-0 CTA (including
//         the ~75% that exit early on empty row tiles) converts a fixed
//         512-float4 chunk of W2 -> fp16 as tail work. No smem cost, no
//         occupancy displacement (lesson from R11's failed z-slice).
// mode 1: out[tok] += gate*(H @ W2 + b2)
// ---------------------------------------------------------------------------
#define GSMEM_BYTES (2 * (ASTAGE + BSTAGE))   // 71680 B
#define NCTA1 (NE * (CAP / BM) * (HID / BN))  // 16384 mode-0 CTAs
#define W2_N4 ((size_t)NE * HID * DIM / 4)    // 8388608 float4s
#define W2_CHUNK (W2_N4 / NCTA1)              // 512 float4 per CTA

__device__ __forceinline__ void w2_convert_chunk(const float* W2src, int flat,
                                                 int tid) {
    size_t base = (size_t)flat * W2_CHUNK;
#pragma unroll
    for (int i = 0; i < (int)(W2_CHUNK / 128); i++)
        ((uint2*)g_W2h)[base + tid + i * 128] =
            cvt4h(((const float4*)W2src)[base + tid + i * 128]);
}

__global__ void __launch_bounds__(128, 2)
moe_gemm_kernel(int mode, const float* __restrict__ bias, float* __restrict__ out,
                const float* __restrict__ W2src) {
    extern __shared__ char dyn_smem[];

    int e = blockIdx.z;
    int tid = threadIdx.x;
    int flat = (e * gridDim.y + blockIdx.y) * gridDim.x + blockIdx.x;

    int cnt = g_cnt[e];
    int row0 = blockIdx.y * BM;
    if (row0 >= cnt) {
        if (mode == 0) w2_convert_chunk(W2src, flat, tid);
        return;
    }
    int valid = cnt - row0;
    int nb0 = blockIdx.x * BN;

    const __half* Ag; const __half* Bg;
    int lda, ldb, Kdim;
    if (mode == 0) {
        Ag = g_X   + (size_t)e * CAP * DIM + (size_t)row0 * DIM;  lda = DIM;
        Bg = g_W1h + (size_t)e * DIM * HID;                       ldb = HID;
        Kdim = DIM;
    } else {
        Ag = g_Hb  + (size_t)e * CAP * HID + (size_t)row0 * HID;  lda = HID;
        Bg = g_W2h + (size_t)e * HID * DIM;                       ldb = DIM;
        Kdim = HID;
    }

    int lane = tid & 31;
    int warp = tid >> 5;
    int wm = warp >> 1;              // 0..1  (M groups of 64)
    int wn = warp & 1;               // 0..1  (N groups of 64)

    // ---- smem layout: [A stage0][A stage1][B stage0][B stage1]
    uint32_t smemA = smem_u32(dyn_smem);
    uint32_t smemB = smemA + 2 * ASTAGE;

    uint32_t aaddr = smemA + (uint32_t)(((wm * 64 + (lane & 15)) * LDA + ((lane >> 4) << 3)) * 2);
    uint32_t bbase = smemB + (uint32_t)(((lane & 15) * LDB + wn * 64 + ((lane >> 4) << 3)) * 2);

    uint32_t adst = smemA + (uint32_t)((((tid >> 3)) * LDA + (tid & 7) * 8) * 2);
    uint32_t bdst = smemB + (uint32_t)((((tid >> 4)) * LDB + (tid & 15) * 8) * 2);
    const __half* asrcp = Ag + (size_t)(tid >> 3) * lda + (tid & 7) * 8;
    const __half* bsrcp = Bg + (size_t)(tid >> 4) * ldb + nb0 + (tid & 15) * 8;
    const int a16 = 16 * lda;        // 16-row global stride (halves)
    const int b8  = 8 * ldb;         // 8-row global stride (halves)

    float acc[4][8][4];
#pragma unroll
    for (int mi = 0; mi < 4; mi++)
#pragma unroll
        for (int nj = 0; nj < 8; nj++)
#pragma unroll
            for (int q = 0; q < 4; q++) acc[mi][nj][q] = 0.f;

    auto load_stage = [&](uint32_t aoff, uint32_t boff) {
#pragma unroll
        for (int p = 0; p < 8; p++)
            cp16(adst + aoff + p * (16 * LDA * 2), asrcp + (size_t)p * a16);
#pragma unroll
        for (int p = 0; p < 8; p++)
            cp16(bdst + boff + p * (8 * LDB * 2), bsrcp + (size_t)p * b8);
        CP_COMMIT();
        asrcp += BK;
        bsrcp += (size_t)BK * ldb;
    };

    // register fragment double buffers
    uint32_t af[2][4][4];
    uint32_t bf[2][8][2];
    auto frag_load = [&](int buf, uint32_t aA, uint32_t bA, int ks) {
        const uint32_t ksa = ks * 32;              // 16 halves
        const uint32_t ksb = ks * 16 * LDB * 2;    // 16 rows
#pragma unroll
        for (int mi = 0; mi < 4; mi++)
            ldsm_x4(af[buf][mi], aA + ksa + mi * (16 * LDA * 2));
#pragma unroll
        for (int j = 0; j < 4; j++) {
            uint32_t r4[4];
            ldsm_x4_t(r4, bA + ksb + j * 32);
            bf[buf][2 * j][0] = r4[0]; bf[buf][2 * j][1] = r4[1];
            bf[buf][2 * j + 1][0] = r4[2]; bf[buf][2 * j + 1][1] = r4[3];
        }
    };

    int nk = Kdim / BK;              // 16 (GEMM1) or 64 (GEMM2)
    load_stage(0, 0);

    uint32_t consA = 0, consB = 0;
    uint32_t prodA = ASTAGE, prodB = BSTAGE;
    for (int kt = 0; kt < nk; kt++) {
        CP_WAIT(0);
        __syncthreads();
        if (kt + 1 < nk) {
            load_stage(prodA, prodB);      // overlaps this kt's compute
            prodA ^= ASTAGE; prodB ^= BSTAGE;
        }

        uint32_t aA = aaddr + consA;
        uint32_t bA = bbase + consB;

        frag_load(0, aA, bA, 0);
#pragma unroll
        for (int ks = 0; ks < 4; ks++) {
            int cb = ks & 1;
            if (ks < 3) frag_load(cb ^ 1, aA, bA, ks + 1);  // hide under HMMAs
#pragma unroll
            for (int mi = 0; mi < 4; mi++)
#pragma unroll
                for (int nj = 0; nj < 8; nj++)
                    mma16816(acc[mi][nj], af[cb][mi], bf[cb][nj]);
        }
        consA ^= ASTAGE; consB ^= BSTAGE;
    }

    // --- Epilogue. acc[mi][nj]: rows wm*64+mi*16+{lane/4,+8}, cols wn*64+nj*8+(lane%4)*2+{0,1}
    if (mode == 0) {
        const float* bp = bias + (size_t)e * HID + nb0;
#pragma unroll
        for (int mi = 0; mi < 4; mi++) {
            int rb = wm * 64 + mi * 16 + (lane >> 2);
#pragma unroll
            for (int hr = 0; hr < 2; hr++) {
                int r = rb + hr * 8;
                if (r < valid) {
                    size_t rowoff = ((size_t)e * CAP + row0 + r) * HID + nb0;
#pragma unroll
                    for (int nj = 0; nj < 8; nj++) {
                        int colc = wn * 64 + nj * 8 + ((lane & 3) << 1);
                        float v0 = acc[mi][nj][hr * 2 + 0] + bp[colc];
                        float v1 = acc[mi][nj][hr * 2 + 1] + bp[colc + 1];
                        __half2 h2 = __floats2half2_rn(gelu_f(v0), gelu_f(v1));
                        *(__half2*)(g_Hb + rowoff + colc) = h2;
                    }
                }
            }
        }
        w2_convert_chunk(W2src, flat, tid);   // tail work, no smem footprint
    } else {
        const float* bp = bias + (size_t)e * DIM + nb0;
#pragma unroll
        for (int mi = 0; mi < 4; mi++) {
            int rb = wm * 64 + mi * 16 + (lane >> 2);
#pragma unroll
            for (int hr = 0; hr < 2; hr++) {
                int r = rb + hr * 8;
                if (r < valid) {
                    int t = g_ptok[e * CAP + row0 + r];
                    float gate = g_pgate[e * CAP + row0 + r];
                    float* orow = out + (size_t)t * DIM + nb0;
#pragma unroll
                    for (int nj = 0; nj < 8; nj++) {
                        int colc = wn * 64 + nj * 8 + ((lane & 3) << 1);
                        float v0 = acc[mi][nj][hr * 2 + 0] + bp[colc];
                        float v1 = acc[mi][nj][hr * 2 + 1] + bp[colc + 1];
                        atomicAdd(orow + colc,     gate * v0);
                        atomicAdd(orow + colc + 1, gate * v1);
                    }
                }
            }
        }
    }
}

// ---------------------------------------------------------------------------
// Launch
// ---------------------------------------------------------------------------
extern "C" void kernel_launch(void* const* d_in, const int* in_sizes, int n_in,
                              void* d_out, int out_size) {
    const float* x  = (const float*)d_in[0];
    const float* Wr = (const float*)d_in[1];
    const float* W1 = (const float*)d_in[2];
    const float* b1 = (const float*)d_in[3];
    const float* W2 = (const float*)d_in[4];
    const float* b2 = (const float*)d_in[5];
    float* out = (float*)d_out;

    static int smem_set = 0;
    if (!smem_set) {
        cudaFuncSetAttribute(moe_gemm_kernel,
                             cudaFuncAttributeMaxDynamicSharedMemorySize,
                             GSMEM_BYTES);
        smem_set = 1;
    }

    // 1. zero expert counters
    zero_cnt_kernel<<<1, 32>>>();
    // 2. merged prep: router+gather || (zero out + W1 convert)
    prep_kernel<<<RBLK + CBLK, 256>>>(x, Wr, W1, out);
    // 3. GEMM1: H = gelu(X @ W1 + b1)  (+ distributed W2 convert tail)
    moe_gemm_kernel<<<dim3(HID / BN, CAP / BM, NE), 128, GSMEM_BYTES>>>(0, b1, nullptr, W2);
    // 4. GEMM2: out += gate * (H @ W2 + b2)
    moe_gemm_kernel<<<dim3(DIM / BN, CAP / BM, NE), 128, GSMEM_BYTES>>>(1, b2, out, nullptr);
}